// round 7
// baseline (speedup 1.0000x reference)
#include <cuda_runtime.h>
#include <cuda_bf16.h>
#include <math.h>

// Problem constants (fixed by setup_inputs)
#define BB      2
#define SEQ     4096
#define DIM     2048
#define NH      16
#define DHALF   64          // Dh/2
#define DHEAD   128
#define NROWS   (BB*SEQ)    // 8192
#define NCHUNK  16
#define CHUNKL  256
#define F3      (3*DIM)     // 6144

// ---------------- scratch (device globals; no allocation allowed) ----------
__device__ float g_xn   [(size_t)NROWS * DIM];   // 64 MB  (normed x)
__device__ float g_xc   [(size_t)NROWS * DIM];   // 64 MB  (conv+silu; later reused for y)
__device__ float g_fused[(size_t)NROWS * F3];    // 192 MB (dt|v|gate -> la|v_in|gate)
__device__ float g_final[(size_t)NROWS * DIM];   // 64 MB  (scan output)
__device__ float g_bd   [BB * NCHUNK * DIM];
__device__ float g_bo   [BB * NCHUNK * DIM];
__device__ float g_carry[BB * NCHUNK * DIM];

// ---------------- packed f32x2 helpers -------------------------------------
__device__ __forceinline__ unsigned long long pack2(float lo, float hi) {
    unsigned long long r;
    asm("mov.b64 %0, {%1,%2};" : "=l"(r) : "f"(lo), "f"(hi));
    return r;
}
__device__ __forceinline__ void fma2(unsigned long long& c,
                                     unsigned long long a, unsigned long long b) {
    asm("fma.rn.f32x2 %0, %1, %2, %0;" : "+l"(c) : "l"(a), "l"(b));
}
__device__ __forceinline__ float2 unpack2(unsigned long long v) {
    float2 f;
    asm("mov.b64 {%0,%1}, %2;" : "=f"(f.x), "=f"(f.y) : "l"(v));
    return f;
}

// ---------------- 1. RMSNorm ------------------------------------------------
__global__ void k_rmsnorm(const float* __restrict__ x,
                          const float* __restrict__ scale) {
    int row = blockIdx.x;
    const float* xr = x + (size_t)row * DIM;
    float*       o  = g_xn + (size_t)row * DIM;

    float s = 0.f;
    for (int i = threadIdx.x; i < DIM; i += blockDim.x) {
        float v = xr[i];
        s += v * v;
    }
    __shared__ float red[32];
    #pragma unroll
    for (int off = 16; off; off >>= 1) s += __shfl_xor_sync(0xffffffffu, s, off);
    if ((threadIdx.x & 31) == 0) red[threadIdx.x >> 5] = s;
    __syncthreads();
    if (threadIdx.x < 32) {
        float t = (threadIdx.x < (blockDim.x >> 5)) ? red[threadIdx.x] : 0.f;
        #pragma unroll
        for (int off = 16; off; off >>= 1) t += __shfl_xor_sync(0xffffffffu, t, off);
        if (threadIdx.x == 0) red[0] = t;
    }
    __syncthreads();
    float rms = rsqrtf(red[0] / (float)DIM + 1e-6f);
    for (int i = threadIdx.x; i < DIM; i += blockDim.x) {
        float v = scale[i] * xr[i] * rms;
        o[i] = fminf(fmaxf(v, -60000.f), 60000.f);
    }
}

// ---------------- 2. depthwise causal conv (K=4) + bias + SiLU -------------
__global__ void k_conv(const float* __restrict__ cw,
                       const float* __restrict__ cb) {
    int idx = blockIdx.x * blockDim.x + threadIdx.x;   // over NROWS*DIM
    if (idx >= NROWS * DIM) return;
    int d   = idx & (DIM - 1);
    int row = idx >> 11;          // /DIM
    int n   = row & (SEQ - 1);

    const float4 w = *reinterpret_cast<const float4*>(&cw[d * 4]);
    float acc = cb[d];
    const float* base = g_xn + (size_t)row * DIM + d;
    // taps: xn[n-3..n] * w[0..3]  (zero pad on the left)
    if (n >= 3) {
        acc += w.x * base[-3 * DIM] + w.y * base[-2 * DIM]
             + w.z * base[-1 * DIM] + w.w * base[0];
    } else {
        if (n >= 3) acc += w.x * base[-3 * DIM];
        if (n >= 2) acc += w.y * base[-2 * DIM];
        if (n >= 1) acc += w.z * base[-1 * DIM];
        acc += w.w * base[0];
    }
    g_xc[idx] = acc / (1.f + expf(-acc));   // silu
}

// ---------------- 3/9. SGEMM: C[M,N] = A[M,K] * B[N,K]^T  (+ residual) -----
// BM=BN=128, BK=16, 256 threads, 8x8 micro-tile via packed f32x2 FMAs.
__global__ __launch_bounds__(256, 2)
void k_gemm(const float* __restrict__ A, const float* __restrict__ Bm,
            float* __restrict__ C, const float* __restrict__ Res,
            int Nn, int Kn) {
    __shared__ __align__(16) float As[16][128];
    __shared__ __align__(16) float Bs[16][128];

    const int tid = threadIdx.x;
    const int tx  = tid & 15;
    const int ty  = tid >> 4;
    const int bx  = blockIdx.x;
    const int by  = blockIdx.y;

    const float* Ab = A  + (size_t)(by * 128) * Kn;
    const float* Bb = Bm + (size_t)(bx * 128) * Kn;

    unsigned long long acc[8][4];
    #pragma unroll
    for (int i = 0; i < 8; i++)
        #pragma unroll
        for (int p = 0; p < 4; p++) acc[i][p] = 0ull;

    for (int kt = 0; kt < Kn; kt += 16) {
        #pragma unroll
        for (int q = 0; q < 2; q++) {
            int l  = tid + q * 256;       // 0..511 float4 slots
            int r  = l >> 2;              // 0..127 tile row
            int c4 = (l & 3) * 4;         // 0,4,8,12
            float4 va = *reinterpret_cast<const float4*>(Ab + (size_t)r * Kn + kt + c4);
            As[c4 + 0][r] = va.x; As[c4 + 1][r] = va.y;
            As[c4 + 2][r] = va.z; As[c4 + 3][r] = va.w;
            float4 vb = *reinterpret_cast<const float4*>(Bb + (size_t)r * Kn + kt + c4);
            Bs[c4 + 0][r] = vb.x; Bs[c4 + 1][r] = vb.y;
            Bs[c4 + 2][r] = vb.z; Bs[c4 + 3][r] = vb.w;
        }
        __syncthreads();

        #pragma unroll
        for (int k = 0; k < 16; k++) {
            float4 a0 = *reinterpret_cast<const float4*>(&As[k][ty * 4]);
            float4 a1 = *reinterpret_cast<const float4*>(&As[k][64 + ty * 4]);
            float4 b0 = *reinterpret_cast<const float4*>(&Bs[k][tx * 4]);
            float4 b1 = *reinterpret_cast<const float4*>(&Bs[k][64 + tx * 4]);

            unsigned long long av[8], bv[4];
            av[0] = pack2(a0.x, a0.x); av[1] = pack2(a0.y, a0.y);
            av[2] = pack2(a0.z, a0.z); av[3] = pack2(a0.w, a0.w);
            av[4] = pack2(a1.x, a1.x); av[5] = pack2(a1.y, a1.y);
            av[6] = pack2(a1.z, a1.z); av[7] = pack2(a1.w, a1.w);
            bv[0] = pack2(b0.x, b0.y); bv[1] = pack2(b0.z, b0.w);
            bv[2] = pack2(b1.x, b1.y); bv[3] = pack2(b1.z, b1.w);

            #pragma unroll
            for (int i = 0; i < 8; i++)
                #pragma unroll
                for (int p = 0; p < 4; p++)
                    fma2(acc[i][p], av[i], bv[p]);
        }
        __syncthreads();
    }

    #pragma unroll
    for (int i = 0; i < 8; i++) {
        int gr = by * 128 + ((i < 4) ? (ty * 4 + i) : (64 + ty * 4 + i - 4));
        float* crow = C + (size_t)gr * Nn + bx * 128;
        const float* rrow = Res ? (Res + (size_t)gr * Nn + bx * 128) : (const float*)0;
        #pragma unroll
        for (int p = 0; p < 4; p++) {
            int col = ((p < 2) ? 0 : 64) + tx * 4 + (p & 1) * 2;
            float2 v = unpack2(acc[i][p]);
            if (Res) {
                float2 r2 = *reinterpret_cast<const float2*>(rrow + col);
                v.x += r2.x; v.y += r2.y;
            }
            *reinterpret_cast<float2*>(crow + col) = v;
        }
    }
}

// ---------------- 4. dt/softplus, RoPE, gate (in place on g_fused) ---------
__global__ void k_post(const float* __restrict__ dt_bias) {
    int idx = blockIdx.x * blockDim.x + threadIdx.x;  // NROWS * NH * 64
    if (idx >= NROWS * NH * DHALF) return;
    int j   = idx & 63;
    int h   = (idx >> 6) & 15;
    int row = idx >> 10;
    int n   = row & (SEQ - 1);

    int d1 = h * DHEAD + j;
    int d2 = d1 + DHALF;
    float* fr = g_fused + (size_t)row * F3;

    // dt = clip(softplus(raw + bias), 0.001, 2)
    float x1 = fr[d1] + dt_bias[d1];
    float x2 = fr[d2] + dt_bias[d2];
    float sp1 = fmaxf(x1, 0.f) + log1pf(expf(-fabsf(x1)));
    float sp2 = fmaxf(x2, 0.f) + log1pf(expf(-fabsf(x2)));
    float dt1 = fminf(fmaxf(sp1, 0.001f), 2.f);
    float dt2 = fminf(fmaxf(sp2, 0.001f), 2.f);
    fr[d1] = -dt1;   // log_alpha
    fr[d2] = -dt2;

    // RoPE
    float invf = powf(10000.0f, -(float)(2 * j) / 128.0f);
    float fr_ang = (float)n * invf;
    float c = cosf(fr_ang), s = sinf(fr_ang);
    float v1 = fr[DIM + d1];
    float v2 = fr[DIM + d2];
    fr[DIM + d1] = (v1 * c - v2 * s) * dt1;   // v_in
    fr[DIM + d2] = (v1 * s + v2 * c) * dt2;

    // gate
    float g1 = fr[2 * DIM + d1];
    float g2 = fr[2 * DIM + d2];
    fr[2 * DIM + d1] = 1.f / (1.f + expf(-g1));
    fr[2 * DIM + d2] = 1.f / (1.f + expf(-g2));
}

// ---------------- 5. within-chunk scan -------------------------------------
__global__ void k_scan() {
    int idx = blockIdx.x * blockDim.x + threadIdx.x;  // BB*NCHUNK*DIM = 65536
    if (idx >= BB * NCHUNK * DIM) return;
    int d  = idx & (DIM - 1);
    int nc = (idx >> 11) & (NCHUNK - 1);
    int b  = idx >> 15;

    size_t rowbase = (size_t)b * SEQ + nc * CHUNKL;
    const float* la = g_fused + rowbase * F3 + d;
    const float* vv = g_fused + rowbase * F3 + DIM + d;
    float*       ot = g_final + rowbase * DIM + d;

    // pass 1: Lmax
    float Ls = 0.f, Lmax = -1e30f;
    for (int i = 0; i < CHUNKL; i++) {
        Ls += la[(size_t)i * F3];
        float L = fminf(fmaxf(Ls, -20.f), 0.f);
        Lmax = fmaxf(Lmax, L);
    }
    // pass 2: stabilized cumulative
    Ls = 0.f;
    float sum = 0.f, lastL = 0.f, lastO = 0.f;
    for (int i = 0; i < CHUNKL; i++) {
        Ls += la[(size_t)i * F3];
        float L  = fminf(fmaxf(Ls, -20.f), 0.f);
        float Lt = L - Lmax;
        sum += expf(-Lt) * vv[(size_t)i * F3];
        float o = expf(Lt) * sum;
        ot[(size_t)i * DIM] = o;
        lastL = L; lastO = o;
    }
    g_bd[idx] = lastL;
    g_bo[idx] = lastO;
}

// ---------------- 6. cross-chunk carry scan --------------------------------
__global__ void k_carry() {
    int idx = blockIdx.x * blockDim.x + threadIdx.x;  // BB*DIM = 4096
    if (idx >= BB * DIM) return;
    int d = idx & (DIM - 1);
    int b = idx >> 11;

    float cd[NCHUNK];
    float run = 0.f, stab = -1e30f;
    #pragma unroll
    for (int nc = 0; nc < NCHUNK; nc++) {
        run += g_bd[(b * NCHUNK + nc) * DIM + d];
        float c = fminf(fmaxf(run, -80.f), 0.f);
        cd[nc] = c;
        stab = fmaxf(stab, c);
    }
    float acc = 0.f;
    #pragma unroll
    for (int nc = 0; nc < NCHUNK; nc++) {
        float ncd = fminf(fmaxf(cd[nc] - stab, -20.f), 0.f);
        g_carry[(b * NCHUNK + nc) * DIM + d] = acc * expf(ncd);
        acc += g_bo[(b * NCHUNK + nc) * DIM + d] * expf(-ncd);
    }
}

// ---------------- 7. apply carries: final += carry * exp(L) ----------------
__global__ void k_final() {
    int idx = blockIdx.x * blockDim.x + threadIdx.x;  // BB*NCHUNK*DIM
    if (idx >= BB * NCHUNK * DIM) return;
    int d  = idx & (DIM - 1);
    int nc = (idx >> 11) & (NCHUNK - 1);
    int b  = idx >> 15;

    float carry = g_carry[idx];
    size_t rowbase = (size_t)b * SEQ + nc * CHUNKL;
    const float* la = g_fused + rowbase * F3 + d;
    float*       ot = g_final + rowbase * DIM + d;

    float Ls = 0.f;
    for (int i = 0; i < CHUNKL; i++) {
        Ls += la[(size_t)i * F3];
        float L = fminf(fmaxf(Ls, -20.f), 0.f);
        ot[(size_t)i * DIM] += carry * expf(L);
    }
}

// ---------------- 8. head mix + gate (y into g_xc) -------------------------
__global__ void k_mix(const float* __restrict__ head_mix) {
    int row = blockIdx.x;
    __shared__ float sf[DIM];
    __shared__ float hm[NH * NH];
    const float* fr = g_final + (size_t)row * DIM;
    const float* gr = g_fused + (size_t)row * F3 + 2 * DIM;
    float*       y  = g_xc + (size_t)row * DIM;

    for (int i = threadIdx.x; i < DIM; i += blockDim.x) sf[i] = fr[i];
    for (int i = threadIdx.x; i < NH * NH; i += blockDim.x) hm[i] = head_mix[i];
    __syncthreads();

    for (int i = threadIdx.x; i < DIM; i += blockDim.x) {
        int dd = i & (DHEAD - 1);
        int m  = i >> 7;
        float acc = 0.f;
        #pragma unroll
        for (int h = 0; h < NH; h++) acc += sf[h * DHEAD + dd] * hm[h * NH + m];
        y[i] = acc * gr[i];
    }
}

// ---------------- launcher --------------------------------------------------
extern "C" void kernel_launch(void* const* d_in, const int* in_sizes, int n_in,
                              void* d_out, int out_size) {
    const float* x          = (const float*)d_in[0];
    const float* norm_scale = (const float*)d_in[1];
    const float* conv_w     = (const float*)d_in[2];
    const float* conv_b     = (const float*)d_in[3];
    const float* in_proj_w  = (const float*)d_in[4];
    const float* dt_bias    = (const float*)d_in[5];
    const float* head_mix   = (const float*)d_in[6];
    const float* out_proj_w = (const float*)d_in[7];
    float* out = (float*)d_out;

    float *p_xc, *p_fused;
    cudaGetSymbolAddress((void**)&p_xc, g_xc);
    cudaGetSymbolAddress((void**)&p_fused, g_fused);

    k_rmsnorm<<<NROWS, 256>>>(x, norm_scale);
    k_conv<<<(NROWS * DIM) / 256, 256>>>(conv_w, conv_b);

    // fused = xc @ in_proj_w^T : M=8192, N=6144, K=2048
    k_gemm<<<dim3(6144 / 128, NROWS / 128), 256>>>(p_xc, in_proj_w, p_fused,
                                                   (const float*)0, 6144, 2048);

    k_post<<<(NROWS * NH * DHALF) / 256, 256>>>(dt_bias);
    k_scan<<<(BB * NCHUNK * DIM) / 256, 256>>>();
    k_carry<<<(BB * DIM) / 256, 256>>>();
    k_final<<<(BB * NCHUNK * DIM) / 256, 256>>>();
    k_mix<<<NROWS, 256>>>(head_mix);

    // out = residual + (vm*gate) @ out_proj_w^T : M=8192, N=2048, K=2048
    k_gemm<<<dim3(2048 / 128, NROWS / 128), 256>>>(p_xc, out_proj_w, out,
                                                   x, 2048, 2048);
}

// round 8
// speedup vs baseline: 1.0001x; 1.0001x over previous
#include <cuda_runtime.h>
#include <cuda_bf16.h>
#include <math.h>

// Problem constants (fixed by setup_inputs)
#define BB      2
#define SEQ     4096
#define DIM     2048
#define NH      16
#define DHALF   64          // Dh/2
#define DHEAD   128
#define NROWS   (BB*SEQ)    // 8192
#define NCHUNK  16
#define CHUNKL  256
#define F3      (3*DIM)     // 6144

// ---------------- scratch (device globals; no allocation allowed) ----------
__device__ float g_xn   [(size_t)NROWS * DIM];   // 64 MB  (normed x)
__device__ float g_xc   [(size_t)NROWS * DIM];   // 64 MB  (conv+silu; later reused for y)
__device__ float g_fused[(size_t)NROWS * F3];    // 192 MB (dt|v|gate -> la|v_in|gate)
__device__ float g_final[(size_t)NROWS * DIM];   // 64 MB  (scan output)
__device__ float g_bd   [BB * NCHUNK * DIM];
__device__ float g_bo   [BB * NCHUNK * DIM];
__device__ float g_carry[BB * NCHUNK * DIM];

// ---------------- packed f32x2 helpers -------------------------------------
__device__ __forceinline__ unsigned long long pack2(float lo, float hi) {
    unsigned long long r;
    asm("mov.b64 %0, {%1,%2};" : "=l"(r) : "f"(lo), "f"(hi));
    return r;
}
__device__ __forceinline__ void fma2(unsigned long long& c,
                                     unsigned long long a, unsigned long long b) {
    asm("fma.rn.f32x2 %0, %1, %2, %0;" : "+l"(c) : "l"(a), "l"(b));
}
__device__ __forceinline__ float2 unpack2(unsigned long long v) {
    float2 f;
    asm("mov.b64 {%0,%1}, %2;" : "=f"(f.x), "=f"(f.y) : "l"(v));
    return f;
}

// ---------------- 1. RMSNorm ------------------------------------------------
__global__ void k_rmsnorm(const float* __restrict__ x,
                          const float* __restrict__ scale) {
    int row = blockIdx.x;
    const float* xr = x + (size_t)row * DIM;
    float*       o  = g_xn + (size_t)row * DIM;

    float s = 0.f;
    for (int i = threadIdx.x; i < DIM; i += blockDim.x) {
        float v = xr[i];
        s += v * v;
    }
    __shared__ float red[32];
    #pragma unroll
    for (int off = 16; off; off >>= 1) s += __shfl_xor_sync(0xffffffffu, s, off);
    if ((threadIdx.x & 31) == 0) red[threadIdx.x >> 5] = s;
    __syncthreads();
    if (threadIdx.x < 32) {
        float t = (threadIdx.x < (blockDim.x >> 5)) ? red[threadIdx.x] : 0.f;
        #pragma unroll
        for (int off = 16; off; off >>= 1) t += __shfl_xor_sync(0xffffffffu, t, off);
        if (threadIdx.x == 0) red[0] = t;
    }
    __syncthreads();
    float rms = rsqrtf(red[0] / (float)DIM + 1e-6f);
    for (int i = threadIdx.x; i < DIM; i += blockDim.x) {
        float v = scale[i] * xr[i] * rms;
        o[i] = fminf(fmaxf(v, -60000.f), 60000.f);
    }
}

// ---------------- 2. depthwise causal conv (K=4) + bias + SiLU -------------
__global__ void k_conv(const float* __restrict__ cw,
                       const float* __restrict__ cb) {
    int idx = blockIdx.x * blockDim.x + threadIdx.x;   // over NROWS*DIM
    if (idx >= NROWS * DIM) return;
    int d   = idx & (DIM - 1);
    int row = idx >> 11;          // /DIM
    int n   = row & (SEQ - 1);

    const float4 w = *reinterpret_cast<const float4*>(&cw[d * 4]);
    float acc = cb[d];
    const float* base = g_xn + (size_t)row * DIM + d;
    // taps: xn[n-3..n] * w[0..3]  (zero pad on the left)
    if (n >= 3) {
        acc += w.x * base[-3 * DIM] + w.y * base[-2 * DIM]
             + w.z * base[-1 * DIM] + w.w * base[0];
    } else {
        if (n >= 3) acc += w.x * base[-3 * DIM];
        if (n >= 2) acc += w.y * base[-2 * DIM];
        if (n >= 1) acc += w.z * base[-1 * DIM];
        acc += w.w * base[0];
    }
    g_xc[idx] = acc / (1.f + expf(-acc));   // silu
}

// ---------------- 3/9. SGEMM: C[M,N] = A[M,K] * B[N,K]^T  (+ residual) -----
// BM=BN=128, BK=16, 256 threads, 8x8 micro-tile via packed f32x2 FMAs.
__global__ __launch_bounds__(256, 2)
void k_gemm(const float* __restrict__ A, const float* __restrict__ Bm,
            float* __restrict__ C, const float* __restrict__ Res,
            int Nn, int Kn) {
    __shared__ __align__(16) float As[16][128];
    __shared__ __align__(16) float Bs[16][128];

    const int tid = threadIdx.x;
    const int tx  = tid & 15;
    const int ty  = tid >> 4;
    const int bx  = blockIdx.x;
    const int by  = blockIdx.y;

    const float* Ab = A  + (size_t)(by * 128) * Kn;
    const float* Bb = Bm + (size_t)(bx * 128) * Kn;

    unsigned long long acc[8][4];
    #pragma unroll
    for (int i = 0; i < 8; i++)
        #pragma unroll
        for (int p = 0; p < 4; p++) acc[i][p] = 0ull;

    for (int kt = 0; kt < Kn; kt += 16) {
        #pragma unroll
        for (int q = 0; q < 2; q++) {
            int l  = tid + q * 256;       // 0..511 float4 slots
            int r  = l >> 2;              // 0..127 tile row
            int c4 = (l & 3) * 4;         // 0,4,8,12
            float4 va = *reinterpret_cast<const float4*>(Ab + (size_t)r * Kn + kt + c4);
            As[c4 + 0][r] = va.x; As[c4 + 1][r] = va.y;
            As[c4 + 2][r] = va.z; As[c4 + 3][r] = va.w;
            float4 vb = *reinterpret_cast<const float4*>(Bb + (size_t)r * Kn + kt + c4);
            Bs[c4 + 0][r] = vb.x; Bs[c4 + 1][r] = vb.y;
            Bs[c4 + 2][r] = vb.z; Bs[c4 + 3][r] = vb.w;
        }
        __syncthreads();

        #pragma unroll
        for (int k = 0; k < 16; k++) {
            float4 a0 = *reinterpret_cast<const float4*>(&As[k][ty * 4]);
            float4 a1 = *reinterpret_cast<const float4*>(&As[k][64 + ty * 4]);
            float4 b0 = *reinterpret_cast<const float4*>(&Bs[k][tx * 4]);
            float4 b1 = *reinterpret_cast<const float4*>(&Bs[k][64 + tx * 4]);

            unsigned long long av[8], bv[4];
            av[0] = pack2(a0.x, a0.x); av[1] = pack2(a0.y, a0.y);
            av[2] = pack2(a0.z, a0.z); av[3] = pack2(a0.w, a0.w);
            av[4] = pack2(a1.x, a1.x); av[5] = pack2(a1.y, a1.y);
            av[6] = pack2(a1.z, a1.z); av[7] = pack2(a1.w, a1.w);
            bv[0] = pack2(b0.x, b0.y); bv[1] = pack2(b0.z, b0.w);
            bv[2] = pack2(b1.x, b1.y); bv[3] = pack2(b1.z, b1.w);

            #pragma unroll
            for (int i = 0; i < 8; i++)
                #pragma unroll
                for (int p = 0; p < 4; p++)
                    fma2(acc[i][p], av[i], bv[p]);
        }
        __syncthreads();
    }

    #pragma unroll
    for (int i = 0; i < 8; i++) {
        int gr = by * 128 + ((i < 4) ? (ty * 4 + i) : (64 + ty * 4 + i - 4));
        float* crow = C + (size_t)gr * Nn + bx * 128;
        const float* rrow = Res ? (Res + (size_t)gr * Nn + bx * 128) : (const float*)0;
        #pragma unroll
        for (int p = 0; p < 4; p++) {
            int col = ((p < 2) ? 0 : 64) + tx * 4 + (p & 1) * 2;
            float2 v = unpack2(acc[i][p]);
            if (Res) {
                float2 r2 = *reinterpret_cast<const float2*>(rrow + col);
                v.x += r2.x; v.y += r2.y;
            }
            *reinterpret_cast<float2*>(crow + col) = v;
        }
    }
}

// ---------------- 4. dt/softplus, RoPE, gate (in place on g_fused) ---------
__global__ void k_post(const float* __restrict__ dt_bias) {
    int idx = blockIdx.x * blockDim.x + threadIdx.x;  // NROWS * NH * 64
    if (idx >= NROWS * NH * DHALF) return;
    int j   = idx & 63;
    int h   = (idx >> 6) & 15;
    int row = idx >> 10;
    int n   = row & (SEQ - 1);

    int d1 = h * DHEAD + j;
    int d2 = d1 + DHALF;
    float* fr = g_fused + (size_t)row * F3;

    // dt = clip(softplus(raw + bias), 0.001, 2)
    float x1 = fr[d1] + dt_bias[d1];
    float x2 = fr[d2] + dt_bias[d2];
    float sp1 = fmaxf(x1, 0.f) + log1pf(expf(-fabsf(x1)));
    float sp2 = fmaxf(x2, 0.f) + log1pf(expf(-fabsf(x2)));
    float dt1 = fminf(fmaxf(sp1, 0.001f), 2.f);
    float dt2 = fminf(fmaxf(sp2, 0.001f), 2.f);
    fr[d1] = -dt1;   // log_alpha
    fr[d2] = -dt2;

    // RoPE
    float invf = powf(10000.0f, -(float)(2 * j) / 128.0f);
    float fr_ang = (float)n * invf;
    float c = cosf(fr_ang), s = sinf(fr_ang);
    float v1 = fr[DIM + d1];
    float v2 = fr[DIM + d2];
    fr[DIM + d1] = (v1 * c - v2 * s) * dt1;   // v_in
    fr[DIM + d2] = (v1 * s + v2 * c) * dt2;

    // gate
    float g1 = fr[2 * DIM + d1];
    float g2 = fr[2 * DIM + d2];
    fr[2 * DIM + d1] = 1.f / (1.f + expf(-g1));
    fr[2 * DIM + d2] = 1.f / (1.f + expf(-g2));
}

// ---------------- 5. within-chunk scan -------------------------------------
__global__ void k_scan() {
    int idx = blockIdx.x * blockDim.x + threadIdx.x;  // BB*NCHUNK*DIM = 65536
    if (idx >= BB * NCHUNK * DIM) return;
    int d  = idx & (DIM - 1);
    int nc = (idx >> 11) & (NCHUNK - 1);
    int b  = idx >> 15;

    size_t rowbase = (size_t)b * SEQ + nc * CHUNKL;
    const float* la = g_fused + rowbase * F3 + d;
    const float* vv = g_fused + rowbase * F3 + DIM + d;
    float*       ot = g_final + rowbase * DIM + d;

    // pass 1: Lmax
    float Ls = 0.f, Lmax = -1e30f;
    for (int i = 0; i < CHUNKL; i++) {
        Ls += la[(size_t)i * F3];
        float L = fminf(fmaxf(Ls, -20.f), 0.f);
        Lmax = fmaxf(Lmax, L);
    }
    // pass 2: stabilized cumulative
    Ls = 0.f;
    float sum = 0.f, lastL = 0.f, lastO = 0.f;
    for (int i = 0; i < CHUNKL; i++) {
        Ls += la[(size_t)i * F3];
        float L  = fminf(fmaxf(Ls, -20.f), 0.f);
        float Lt = L - Lmax;
        sum += expf(-Lt) * vv[(size_t)i * F3];
        float o = expf(Lt) * sum;
        ot[(size_t)i * DIM] = o;
        lastL = L; lastO = o;
    }
    g_bd[idx] = lastL;
    g_bo[idx] = lastO;
}

// ---------------- 6. cross-chunk carry scan --------------------------------
__global__ void k_carry() {
    int idx = blockIdx.x * blockDim.x + threadIdx.x;  // BB*DIM = 4096
    if (idx >= BB * DIM) return;
    int d = idx & (DIM - 1);
    int b = idx >> 11;

    float cd[NCHUNK];
    float run = 0.f, stab = -1e30f;
    #pragma unroll
    for (int nc = 0; nc < NCHUNK; nc++) {
        run += g_bd[(b * NCHUNK + nc) * DIM + d];
        float c = fminf(fmaxf(run, -80.f), 0.f);
        cd[nc] = c;
        stab = fmaxf(stab, c);
    }
    float acc = 0.f;
    #pragma unroll
    for (int nc = 0; nc < NCHUNK; nc++) {
        float ncd = fminf(fmaxf(cd[nc] - stab, -20.f), 0.f);
        g_carry[(b * NCHUNK + nc) * DIM + d] = acc * expf(ncd);
        acc += g_bo[(b * NCHUNK + nc) * DIM + d] * expf(-ncd);
    }
}

// ---------------- 7. apply carries: final += carry * exp(L) ----------------
__global__ void k_final() {
    int idx = blockIdx.x * blockDim.x + threadIdx.x;  // BB*NCHUNK*DIM
    if (idx >= BB * NCHUNK * DIM) return;
    int d  = idx & (DIM - 1);
    int nc = (idx >> 11) & (NCHUNK - 1);
    int b  = idx >> 15;

    float carry = g_carry[idx];
    size_t rowbase = (size_t)b * SEQ + nc * CHUNKL;
    const float* la = g_fused + rowbase * F3 + d;
    float*       ot = g_final + rowbase * DIM + d;

    float Ls = 0.f;
    for (int i = 0; i < CHUNKL; i++) {
        Ls += la[(size_t)i * F3];
        float L = fminf(fmaxf(Ls, -20.f), 0.f);
        ot[(size_t)i * DIM] += carry * expf(L);
    }
}

// ---------------- 8. head mix + gate (y into g_xc) -------------------------
__global__ void k_mix(const float* __restrict__ head_mix) {
    int row = blockIdx.x;
    __shared__ float sf[DIM];
    __shared__ float hm[NH * NH];
    const float* fr = g_final + (size_t)row * DIM;
    const float* gr = g_fused + (size_t)row * F3 + 2 * DIM;
    float*       y  = g_xc + (size_t)row * DIM;

    for (int i = threadIdx.x; i < DIM; i += blockDim.x) sf[i] = fr[i];
    for (int i = threadIdx.x; i < NH * NH; i += blockDim.x) hm[i] = head_mix[i];
    __syncthreads();

    for (int i = threadIdx.x; i < DIM; i += blockDim.x) {
        int dd = i & (DHEAD - 1);
        int m  = i >> 7;
        float acc = 0.f;
        #pragma unroll
        for (int h = 0; h < NH; h++) acc += sf[h * DHEAD + dd] * hm[h * NH + m];
        y[i] = acc * gr[i];
    }
}

// ---------------- launcher --------------------------------------------------
extern "C" void kernel_launch(void* const* d_in, const int* in_sizes, int n_in,
                              void* d_out, int out_size) {
    const float* x          = (const float*)d_in[0];
    const float* norm_scale = (const float*)d_in[1];
    const float* conv_w     = (const float*)d_in[2];
    const float* conv_b     = (const float*)d_in[3];
    const float* in_proj_w  = (const float*)d_in[4];
    const float* dt_bias    = (const float*)d_in[5];
    const float* head_mix   = (const float*)d_in[6];
    const float* out_proj_w = (const float*)d_in[7];
    float* out = (float*)d_out;

    float *p_xc, *p_fused;
    cudaGetSymbolAddress((void**)&p_xc, g_xc);
    cudaGetSymbolAddress((void**)&p_fused, g_fused);

    k_rmsnorm<<<NROWS, 256>>>(x, norm_scale);
    k_conv<<<(NROWS * DIM) / 256, 256>>>(conv_w, conv_b);

    // fused = xc @ in_proj_w^T : M=8192, N=6144, K=2048
    k_gemm<<<dim3(6144 / 128, NROWS / 128), 256>>>(p_xc, in_proj_w, p_fused,
                                                   (const float*)0, 6144, 2048);

    k_post<<<(NROWS * NH * DHALF) / 256, 256>>>(dt_bias);
    k_scan<<<(BB * NCHUNK * DIM) / 256, 256>>>();
    k_carry<<<(BB * DIM) / 256, 256>>>();
    k_final<<<(BB * NCHUNK * DIM) / 256, 256>>>();
    k_mix<<<NROWS, 256>>>(head_mix);

    // out = residual + (vm*gate) @ out_proj_w^T : M=8192, N=2048, K=2048
    k_gemm<<<dim3(2048 / 128, NROWS / 128), 256>>>(p_xc, out_proj_w, out,
                                                   x, 2048, 2048);
}